// round 3
// baseline (speedup 1.0000x reference)
#include <cuda_runtime.h>
#include <math.h>

// Problem constants (fixed by the dataset)
#define NN 100000
#define NE 3200000
#define EPS 1e-5f

// ---------------- scratch (static device globals; no allocation) -------------
__device__ float g_deg[NN];
__device__ float g_dis[NN];
__device__ float g_sc[NN];          // self-loop coef = 1/deg
__device__ float g_coef[NE];        // edge coef = dis[src]*dis[dst]
__device__ __align__(16) float g_T[(size_t)NN * 128];   // transformed features t = h@W
__device__ __align__(16) float g_A[(size_t)NN * 128];   // agg ping
__device__ __align__(16) float g_B[(size_t)NN * 128];   // agg pong
__device__ float g_t4[NN];
__device__ float g_a4[NN];

// ---------------- degree / coef ----------------------------------------------
__global__ void k_init_deg(float* deg) {
    int i = blockIdx.x * blockDim.x + threadIdx.x;
    if (i < NN) deg[i] = 1.0f;   // self-loop
}

__global__ void k_count_deg(const int* __restrict__ dst, float* deg) {
    int e = blockIdx.x * blockDim.x + threadIdx.x;
    if (e < NE) atomicAdd(&deg[dst[e]], 1.0f);
}

__global__ void k_dis(const float* __restrict__ deg, float* dis, float* sc) {
    int i = blockIdx.x * blockDim.x + threadIdx.x;
    if (i < NN) {
        float d = deg[i];
        dis[i] = rsqrtf(d);
        sc[i]  = 1.0f / d;
    }
}

__global__ void k_coef(const int* __restrict__ src, const int* __restrict__ dst,
                       const float* __restrict__ dis, float* coef) {
    int e = blockIdx.x * blockDim.x + threadIdx.x;
    if (e < NE) coef[e] = dis[src[e]] * dis[dst[e]];
}

// ---------------- fused GEMM + self-term + bias init -------------------------
// t[node]   = act(in[node]) @ W           (act = bn+elu if BN, else identity)
// agg[node] = t[node] * sc[node] + b      (scatter kernel then adds edge terms)
template<int DIN, int DOUT, bool BN>
__global__ void k_gemm_init(const float* __restrict__ in,
                            const float* __restrict__ W,
                            const float* __restrict__ b,
                            const float* __restrict__ sc,
                            const float* __restrict__ bg, const float* __restrict__ bbe,
                            const float* __restrict__ bm, const float* __restrict__ bv,
                            float* __restrict__ t, float* __restrict__ agg) {
    constexpr int OX  = DOUT / 4;        // float4 output groups per node
    constexpr int NPB = 256 / OX;        // nodes per block
    __shared__ __align__(16) float Ws[DIN * DOUT];
    __shared__ float xs[NPB][DIN + 1];
    __shared__ float scale_s[DIN];
    __shared__ float shift_s[DIN];
    __shared__ __align__(16) float bsh[DOUT];

    const int tid = threadIdx.x;

    // phase 1: weights, bias, bn params
    for (int i = tid; i < DIN * DOUT; i += 256) Ws[i] = W[i];
    if (tid < DOUT) bsh[tid] = b[tid];
    if (BN) {
        if (tid < DIN) {
            float s = bg[tid] * rsqrtf(bv[tid] + EPS);
            scale_s[tid] = s;
            shift_s[tid] = bbe[tid] - bm[tid] * s;
        }
    }
    __syncthreads();

    // phase 2: load input tile, applying bn+elu inline (fused epilogue of prev layer)
    const int base = blockIdx.x * NPB;
    for (int i = tid; i < NPB * DIN; i += 256) {
        int r = i / DIN, k = i - r * DIN;
        int node = base + r;
        float val = 0.0f;
        if (node < NN) {
            val = in[(size_t)node * DIN + k];
            if (BN) {
                val = val * scale_s[k] + shift_s[k];
                val = (val > 0.0f) ? val : expm1f(val);
            }
        }
        xs[r][k] = val;
    }
    __syncthreads();

    // phase 3: compute
    const int ox = tid % OX;
    const int r  = tid / OX;
    const int node = base + r;
    if (node >= NN) return;

    float4 acc = make_float4(0.f, 0.f, 0.f, 0.f);
#pragma unroll
    for (int k = 0; k < DIN; ++k) {
        float xv = xs[r][k];
        float4 w = *reinterpret_cast<const float4*>(&Ws[k * DOUT + ox * 4]);
        acc.x += xv * w.x; acc.y += xv * w.y;
        acc.z += xv * w.z; acc.w += xv * w.w;
    }
    size_t off = (size_t)node * DOUT + ox * 4;
    *reinterpret_cast<float4*>(&t[off]) = acc;

    float s  = sc[node];
    float4 bb = *reinterpret_cast<const float4*>(&bsh[ox * 4]);
    float4 av = make_float4(acc.x * s + bb.x, acc.y * s + bb.y,
                            acc.z * s + bb.z, acc.w * s + bb.w);
    *reinterpret_cast<float4*>(&agg[off]) = av;
}

// ---------------- edge scatter: agg[dst] += t[src]*coef ----------------------
template<int DOUT>
__global__ void k_scatter(const float* __restrict__ t, const float* __restrict__ coef,
                          const int* __restrict__ src, const int* __restrict__ dst,
                          float* __restrict__ agg) {
    constexpr int TPE = DOUT / 4;                       // threads per edge
    int gid = blockIdx.x * blockDim.x + threadIdx.x;    // <= E*TPE = 102.4M, fits int
    int e = gid / TPE;
    int c = (gid - e * TPE) * 4;
    if (e >= NE) return;
    int s = src[e], d = dst[e];
    float cf = coef[e];
    float4 v = *reinterpret_cast<const float4*>(&t[(size_t)s * DOUT + c]);
    float* addr = &agg[(size_t)d * DOUT + c];
    asm volatile("red.global.add.v4.f32 [%0], {%1, %2, %3, %4};"
                 :: "l"(addr), "f"(v.x * cf), "f"(v.y * cf),
                    "f"(v.z * cf), "f"(v.w * cf)
                 : "memory");
}

// ---------------- layer 4 (DOUT=1): bn3+elu then dot with W4 -----------------
__global__ void k_layer4(const float* __restrict__ in, const float* __restrict__ W4,
                         const float* __restrict__ b4, const float* __restrict__ sc,
                         const float* __restrict__ bg, const float* __restrict__ bbe,
                         const float* __restrict__ bm, const float* __restrict__ bv,
                         float* __restrict__ t4, float* __restrict__ agg4) {
    __shared__ float scale_s[128], shift_s[128], w_s[128];
    int tid = threadIdx.x;
    if (tid < 128) {
        float s = bg[tid] * rsqrtf(bv[tid] + EPS);
        scale_s[tid] = s;
        shift_s[tid] = bbe[tid] - bm[tid] * s;
        w_s[tid] = W4[tid];
    }
    __syncthreads();
    int warp = tid >> 5, lane = tid & 31;
    int node = blockIdx.x * 8 + warp;            // 256 threads = 8 warps = 8 nodes
    if (node >= NN) return;
    float acc = 0.0f;
#pragma unroll
    for (int j = 0; j < 4; ++j) {
        int k = j * 32 + lane;
        float x = in[(size_t)node * 128 + k];
        x = x * scale_s[k] + shift_s[k];
        x = (x > 0.0f) ? x : expm1f(x);
        acc += x * w_s[k];
    }
#pragma unroll
    for (int o = 16; o > 0; o >>= 1) acc += __shfl_xor_sync(0xffffffffu, acc, o);
    if (lane == 0) {
        t4[node] = acc;
        agg4[node] = acc * sc[node] + b4[0];
    }
}

__global__ void k_scatter1(const float* __restrict__ t4, const float* __restrict__ coef,
                           const int* __restrict__ src, const int* __restrict__ dst,
                           float* __restrict__ agg4) {
    int e = blockIdx.x * blockDim.x + threadIdx.x;
    if (e >= NE) return;
    atomicAdd(&agg4[dst[e]], t4[src[e]] * coef[e]);
}

__global__ void k_final(const float* __restrict__ agg4, float* __restrict__ out) {
    int i = blockIdx.x * blockDim.x + threadIdx.x;
    if (i >= NN) return;
    float x = agg4[i];
    x = (x > 0.0f) ? x : expm1f(x);      // elu
    out[i] = 1.0f / (1.0f + expf(-x));   // sigmoid
}

// ---------------- launch -----------------------------------------------------
extern "C" void kernel_launch(void* const* d_in, const int* in_sizes, int n_in,
                              void* d_out, int out_size) {
    const float* x   = (const float*)d_in[0];
    const int*   src = (const int*)  d_in[1];
    const int*   dst = (const int*)  d_in[2];
    const float* W1 = (const float*)d_in[3];  const float* b1 = (const float*)d_in[4];
    const float* W2 = (const float*)d_in[5];  const float* b2 = (const float*)d_in[6];
    const float* W3 = (const float*)d_in[7];  const float* b3 = (const float*)d_in[8];
    const float* W4 = (const float*)d_in[9];  const float* b4 = (const float*)d_in[10];
    const float* g1 = (const float*)d_in[11]; const float* be1 = (const float*)d_in[12];
    const float* m1 = (const float*)d_in[13]; const float* v1  = (const float*)d_in[14];
    const float* g2 = (const float*)d_in[15]; const float* be2 = (const float*)d_in[16];
    const float* m2 = (const float*)d_in[17]; const float* v2  = (const float*)d_in[18];
    const float* g3 = (const float*)d_in[19]; const float* be3 = (const float*)d_in[20];
    const float* m3 = (const float*)d_in[21]; const float* v3  = (const float*)d_in[22];
    float* out = (float*)d_out;

    void *pdeg, *pdis, *psc, *pcoef, *pT, *pA, *pB, *pt4, *pa4;
    cudaGetSymbolAddress(&pdeg, g_deg);
    cudaGetSymbolAddress(&pdis, g_dis);
    cudaGetSymbolAddress(&psc,  g_sc);
    cudaGetSymbolAddress(&pcoef, g_coef);
    cudaGetSymbolAddress(&pT, g_T);
    cudaGetSymbolAddress(&pA, g_A);
    cudaGetSymbolAddress(&pB, g_B);
    cudaGetSymbolAddress(&pt4, g_t4);
    cudaGetSymbolAddress(&pa4, g_a4);
    float* deg = (float*)pdeg; float* dis = (float*)pdis; float* sc = (float*)psc;
    float* coef = (float*)pcoef;
    float* T = (float*)pT; float* A = (float*)pA; float* B = (float*)pB;
    float* t4 = (float*)pt4; float* a4 = (float*)pa4;

    const int TB = 256;
    const int gN = (NN + TB - 1) / TB;
    const int gE = (NE + TB - 1) / TB;

    // normalization coefficients
    k_init_deg<<<gN, TB>>>(deg);
    k_count_deg<<<gE, TB>>>(dst, deg);
    k_dis<<<gN, TB>>>(deg, dis, sc);
    k_coef<<<gE, TB>>>(src, dst, dis, coef);

    // layer 1: 128 -> 32 (no BN on input)
    {
        constexpr int NPB = 256 / (32 / 4);
        k_gemm_init<128, 32, false><<<(NN + NPB - 1) / NPB, TB>>>(
            x, W1, b1, sc, nullptr, nullptr, nullptr, nullptr, T, A);
        k_scatter<32><<<(NE * (32 / 4) + TB - 1) / TB, TB>>>(T, coef, src, dst, A);
    }
    // layer 2: 32 -> 64 (bn1+elu fused into input load)
    {
        constexpr int NPB = 256 / (64 / 4);
        k_gemm_init<32, 64, true><<<(NN + NPB - 1) / NPB, TB>>>(
            A, W2, b2, sc, g1, be1, m1, v1, T, B);
        k_scatter<64><<<(NE * (64 / 4) + TB - 1) / TB, TB>>>(T, coef, src, dst, B);
    }
    // layer 3: 64 -> 128 (bn2+elu fused)
    {
        constexpr int NPB = 256 / (128 / 4);
        k_gemm_init<64, 128, true><<<(NN + NPB - 1) / NPB, TB>>>(
            B, W3, b3, sc, g2, be2, m2, v2, T, A);
        k_scatter<128><<<(NE * (128 / 4) + TB - 1) / TB, TB>>>(T, coef, src, dst, A);
    }
    // layer 4: 128 -> 1 (bn3+elu fused), then elu+sigmoid
    k_layer4<<<(NN + 7) / 8, TB>>>(A, W4, b4, sc, g3, be3, m3, v3, t4, a4);
    k_scatter1<<<gE, TB>>>(t4, coef, src, dst, a4);
    k_final<<<gN, TB>>>(a4, out);
}

// round 5
// speedup vs baseline: 1.2411x; 1.2411x over previous
#include <cuda_runtime.h>
#include <math.h>

#define NN 100000
#define NE 3200000
#define EPS 1e-5f

// ---------------- scratch (static device globals; no allocation) -------------
__device__ int   g_cnt[NN];               // in-degree (without self loop)
__device__ int   g_rowptr[NN + 1];        // CSR row pointers (by dst)
__device__ int   g_cursor[NN];            // fill cursors
__device__ float g_dis[NN];               // deg^-1/2
__device__ float g_sc[NN];                // 1/deg (self-loop coef)
__device__ int   g_psrc[NE];              // permuted src (grouped by dst)
__device__ float g_pcoef[NE];             // permuted edge coef
__device__ __align__(16) float g_T[(size_t)NN * 128];   // t = act(h) @ W
__device__ __align__(16) float g_A[(size_t)NN * 128];   // agg ping
__device__ __align__(16) float g_B[(size_t)NN * 128];   // agg pong
__device__ float g_t4[NN];

// ---------------- CSR build ---------------------------------------------------
__global__ void __launch_bounds__(256) k_zero_cnt(int* cnt) {
    int i = blockIdx.x * blockDim.x + threadIdx.x;
    if (i < NN) cnt[i] = 0;
}

__global__ void __launch_bounds__(256) k_count(const int* __restrict__ dst, int* cnt) {
    int e = blockIdx.x * blockDim.x + threadIdx.x;
    if (e < NE) atomicAdd(&cnt[dst[e]], 1);
}

// single-block scan: rowptr/cursor = exclusive prefix of cnt; dis/sc from deg=cnt+1
__global__ void __launch_bounds__(1024) k_scan(const int* __restrict__ cnt,
                                               int* rowptr, int* cursor,
                                               float* dis, float* sc) {
    __shared__ int part[1024];
    constexpr int CH = (NN + 1023) / 1024;   // 98
    const int tid = threadIdx.x;
    const int beg = tid * CH;
    const int end = (beg + CH < NN) ? beg + CH : NN;
    int sum = 0;
    for (int i = beg; i < end; ++i) sum += cnt[i];
    part[tid] = sum;
    __syncthreads();
    for (int o = 1; o < 1024; o <<= 1) {
        int v = 0;
        if (tid >= o) v = part[tid - o];
        __syncthreads();
        if (tid >= o) part[tid] += v;
        __syncthreads();
    }
    int run = (tid > 0) ? part[tid - 1] : 0;
    for (int i = beg; i < end; ++i) {
        rowptr[i] = run;
        cursor[i] = run;
        int c = cnt[i];
        run += c;
        float d = (float)(c + 1);
        dis[i] = rsqrtf(d);
        sc[i]  = 1.0f / d;
    }
    if (tid == 1023) rowptr[NN] = part[1023];
}

// permute edges into dst-grouped order; fuse coef computation
__global__ void __launch_bounds__(256) k_permute(const int* __restrict__ src,
                                                 const int* __restrict__ dst,
                                                 const float* __restrict__ dis,
                                                 int* cursor,
                                                 int* psrc, float* pcoef) {
    int e = blockIdx.x * blockDim.x + threadIdx.x;
    if (e >= NE) return;
    int s = src[e], d = dst[e];
    int pos = atomicAdd(&cursor[d], 1);
    psrc[pos]  = s;
    pcoef[pos] = dis[s] * dis[d];
}

// ---------------- fused GEMM: t = act(in) @ W ---------------------------------
template<int DIN, int DOUT, bool BN>
__global__ void __launch_bounds__(256) k_gemm(const float* __restrict__ in,
                       const float* __restrict__ W,
                       const float* __restrict__ bg, const float* __restrict__ bbe,
                       const float* __restrict__ bm, const float* __restrict__ bv,
                       float* __restrict__ t) {
    constexpr int OX  = DOUT / 4;
    constexpr int NPB = 256 / OX;
    __shared__ __align__(16) float Ws[DIN * DOUT];
    __shared__ float xs[NPB][DIN + 1];
    __shared__ float scale_s[DIN];
    __shared__ float shift_s[DIN];

    const int tid = threadIdx.x;
    for (int i = tid; i < DIN * DOUT; i += 256) Ws[i] = W[i];
    if (BN) {
        if (tid < DIN) {
            float s = bg[tid] * rsqrtf(bv[tid] + EPS);
            scale_s[tid] = s;
            shift_s[tid] = bbe[tid] - bm[tid] * s;
        }
    }
    __syncthreads();

    const int base = blockIdx.x * NPB;
    for (int i = tid; i < NPB * DIN; i += 256) {
        int r = i / DIN, k = i - r * DIN;
        int node = base + r;
        float val = 0.0f;
        if (node < NN) {
            val = in[(size_t)node * DIN + k];
            if (BN) {
                val = val * scale_s[k] + shift_s[k];
                val = (val > 0.0f) ? val : expm1f(val);
            }
        }
        xs[r][k] = val;
    }
    __syncthreads();

    const int ox = tid % OX;
    const int r  = tid / OX;
    const int node = base + r;
    if (node >= NN) return;

    float4 acc = make_float4(0.f, 0.f, 0.f, 0.f);
#pragma unroll
    for (int k = 0; k < DIN; ++k) {
        float xv = xs[r][k];
        float4 w = *reinterpret_cast<const float4*>(&Ws[k * DOUT + ox * 4]);
        acc.x += xv * w.x; acc.y += xv * w.y;
        acc.z += xv * w.z; acc.w += xv * w.w;
    }
    *reinterpret_cast<float4*>(&t[(size_t)node * DOUT + ox * 4]) = acc;
}

// ---------------- warp-per-dst CSR gather: agg = sum + self + bias ------------
template<int DOUT>
__global__ void __launch_bounds__(256) k_gather(const float* __restrict__ t,
                         const int* __restrict__ rowptr,
                         const int* __restrict__ psrc,
                         const float* __restrict__ pcoef,
                         const float* __restrict__ sc,
                         const float* __restrict__ b,
                         float* __restrict__ agg) {
    constexpr int V = DOUT / 32;   // floats per lane
    const int warp = (blockIdx.x * blockDim.x + threadIdx.x) >> 5;
    const int lane = threadIdx.x & 31;
    if (warp >= NN) return;
    const int node = warp;
    const int beg = rowptr[node], end = rowptr[node + 1];

    float acc[V];
#pragma unroll
    for (int j = 0; j < V; ++j) acc[j] = 0.0f;

    int i = beg;
    // unroll x4: 4 independent row-gathers in flight per iteration (MLP vs L2 lat)
    for (; i + 3 < end; i += 4) {
        int   s0 = psrc[i],   s1 = psrc[i+1], s2 = psrc[i+2], s3 = psrc[i+3];
        float c0 = pcoef[i],  c1 = pcoef[i+1], c2 = pcoef[i+2], c3 = pcoef[i+3];
        const float* p0 = &t[(size_t)s0 * DOUT + lane * V];
        const float* p1 = &t[(size_t)s1 * DOUT + lane * V];
        const float* p2 = &t[(size_t)s2 * DOUT + lane * V];
        const float* p3 = &t[(size_t)s3 * DOUT + lane * V];
        if constexpr (V == 4) {
            float4 v0 = *reinterpret_cast<const float4*>(p0);
            float4 v1 = *reinterpret_cast<const float4*>(p1);
            float4 v2 = *reinterpret_cast<const float4*>(p2);
            float4 v3 = *reinterpret_cast<const float4*>(p3);
            acc[0] += c0*v0.x + c1*v1.x + c2*v2.x + c3*v3.x;
            acc[1] += c0*v0.y + c1*v1.y + c2*v2.y + c3*v3.y;
            acc[2] += c0*v0.z + c1*v1.z + c2*v2.z + c3*v3.z;
            acc[3] += c0*v0.w + c1*v1.w + c2*v2.w + c3*v3.w;
        } else if constexpr (V == 2) {
            float2 v0 = *reinterpret_cast<const float2*>(p0);
            float2 v1 = *reinterpret_cast<const float2*>(p1);
            float2 v2 = *reinterpret_cast<const float2*>(p2);
            float2 v3 = *reinterpret_cast<const float2*>(p3);
            acc[0] += c0*v0.x + c1*v1.x + c2*v2.x + c3*v3.x;
            acc[1] += c0*v0.y + c1*v1.y + c2*v2.y + c3*v3.y;
        } else {
            acc[0] += c0*p0[0] + c1*p1[0] + c2*p2[0] + c3*p3[0];
        }
    }
    for (; i < end; ++i) {
        int s0 = psrc[i];
        float c0 = pcoef[i];
        const float* p0 = &t[(size_t)s0 * DOUT + lane * V];
        if constexpr (V == 4) {
            float4 v0 = *reinterpret_cast<const float4*>(p0);
            acc[0] += c0 * v0.x; acc[1] += c0 * v0.y;
            acc[2] += c0 * v0.z; acc[3] += c0 * v0.w;
        } else if constexpr (V == 2) {
            float2 v0 = *reinterpret_cast<const float2*>(p0);
            acc[0] += c0 * v0.x; acc[1] += c0 * v0.y;
        } else {
            acc[0] += c0 * p0[0];
        }
    }

    // self-loop + bias
    const float s = sc[node];
    const float* ps = &t[(size_t)node * DOUT + lane * V];
    float* pa = &agg[(size_t)node * DOUT + lane * V];
    if constexpr (V == 4) {
        float4 v = *reinterpret_cast<const float4*>(ps);
        float4 bb = *reinterpret_cast<const float4*>(&b[lane * 4]);
        float4 o = make_float4(acc[0] + v.x * s + bb.x, acc[1] + v.y * s + bb.y,
                               acc[2] + v.z * s + bb.z, acc[3] + v.w * s + bb.w);
        *reinterpret_cast<float4*>(pa) = o;
    } else if constexpr (V == 2) {
        float2 v = *reinterpret_cast<const float2*>(ps);
        float2 bb = *reinterpret_cast<const float2*>(&b[lane * 2]);
        float2 o = make_float2(acc[0] + v.x * s + bb.x, acc[1] + v.y * s + bb.y);
        *reinterpret_cast<float2*>(pa) = o;
    } else {
        pa[0] = acc[0] + ps[0] * s + b[lane];
    }
}

// ---------------- layer 4 (DOUT=1): bn3+elu then dot with W4 ------------------
__global__ void __launch_bounds__(256) k_layer4(const float* __restrict__ in,
                         const float* __restrict__ W4,
                         const float* __restrict__ bg, const float* __restrict__ bbe,
                         const float* __restrict__ bm, const float* __restrict__ bv,
                         float* __restrict__ t4) {
    __shared__ float scale_s[128], shift_s[128], w_s[128];
    int tid = threadIdx.x;
    if (tid < 128) {
        float s = bg[tid] * rsqrtf(bv[tid] + EPS);
        scale_s[tid] = s;
        shift_s[tid] = bbe[tid] - bm[tid] * s;
        w_s[tid] = W4[tid];
    }
    __syncthreads();
    int warp = tid >> 5, lane = tid & 31;
    int node = blockIdx.x * 8 + warp;
    if (node >= NN) return;
    float acc = 0.0f;
#pragma unroll
    for (int j = 0; j < 4; ++j) {
        int k = j * 32 + lane;
        float x = in[(size_t)node * 128 + k];
        x = x * scale_s[k] + shift_s[k];
        x = (x > 0.0f) ? x : expm1f(x);
        acc += x * w_s[k];
    }
#pragma unroll
    for (int o = 16; o > 0; o >>= 1) acc += __shfl_xor_sync(0xffffffffu, acc, o);
    if (lane == 0) t4[node] = acc;
}

// warp-per-dst gather for DOUT=1, fused elu+sigmoid epilogue -> out
__global__ void __launch_bounds__(256) k_gather1_final(const float* __restrict__ t4,
                                const int* __restrict__ rowptr,
                                const int* __restrict__ psrc,
                                const float* __restrict__ pcoef,
                                const float* __restrict__ sc,
                                const float* __restrict__ b4,
                                float* __restrict__ out) {
    const int warp = (blockIdx.x * blockDim.x + threadIdx.x) >> 5;
    const int lane = threadIdx.x & 31;
    if (warp >= NN) return;
    const int node = warp;
    const int beg = rowptr[node], end = rowptr[node + 1];
    float acc = 0.0f;
    for (int i = beg + lane; i < end; i += 32)
        acc += pcoef[i] * t4[psrc[i]];
#pragma unroll
    for (int o = 16; o > 0; o >>= 1) acc += __shfl_xor_sync(0xffffffffu, acc, o);
    if (lane == 0) {
        float x = acc + t4[node] * sc[node] + b4[0];
        x = (x > 0.0f) ? x : expm1f(x);       // elu
        out[node] = 1.0f / (1.0f + expf(-x)); // sigmoid
    }
}

// ---------------- launch -----------------------------------------------------
extern "C" void kernel_launch(void* const* d_in, const int* in_sizes, int n_in,
                              void* d_out, int out_size) {
    const float* x   = (const float*)d_in[0];
    const int*   src = (const int*)  d_in[1];
    const int*   dst = (const int*)  d_in[2];
    const float* W1 = (const float*)d_in[3];  const float* b1 = (const float*)d_in[4];
    const float* W2 = (const float*)d_in[5];  const float* b2 = (const float*)d_in[6];
    const float* W3 = (const float*)d_in[7];  const float* b3 = (const float*)d_in[8];
    const float* W4 = (const float*)d_in[9];  const float* b4 = (const float*)d_in[10];
    const float* g1 = (const float*)d_in[11]; const float* be1 = (const float*)d_in[12];
    const float* m1 = (const float*)d_in[13]; const float* v1  = (const float*)d_in[14];
    const float* g2 = (const float*)d_in[15]; const float* be2 = (const float*)d_in[16];
    const float* m2 = (const float*)d_in[17]; const float* v2  = (const float*)d_in[18];
    const float* g3 = (const float*)d_in[19]; const float* be3 = (const float*)d_in[20];
    const float* m3 = (const float*)d_in[21]; const float* v3  = (const float*)d_in[22];
    float* out = (float*)d_out;

    void *pcnt, *prp, *pcur, *pdis, *psc, *ppsrc, *ppc, *pT, *pA, *pB, *pt4;
    cudaGetSymbolAddress(&pcnt, g_cnt);
    cudaGetSymbolAddress(&prp,  g_rowptr);
    cudaGetSymbolAddress(&pcur, g_cursor);
    cudaGetSymbolAddress(&pdis, g_dis);
    cudaGetSymbolAddress(&psc,  g_sc);
    cudaGetSymbolAddress(&ppsrc, g_psrc);
    cudaGetSymbolAddress(&ppc,   g_pcoef);
    cudaGetSymbolAddress(&pT, g_T);
    cudaGetSymbolAddress(&pA, g_A);
    cudaGetSymbolAddress(&pB, g_B);
    cudaGetSymbolAddress(&pt4, g_t4);
    int* cnt = (int*)pcnt; int* rowptr = (int*)prp; int* cursor = (int*)pcur;
    float* dis = (float*)pdis; float* sc = (float*)psc;
    int* perm_src = (int*)ppsrc; float* perm_coef = (float*)ppc;
    float* T = (float*)pT; float* A = (float*)pA; float* B = (float*)pB;
    float* t4 = (float*)pt4;

    const int TB = 256;
    const int gN = (NN + TB - 1) / TB;
    const int gE = (NE + TB - 1) / TB;
    const int gW = (NN + 7) / 8;          // warp-per-node kernels, 8 warps/block

    // CSR build (by dst) + normalization coefficients
    k_zero_cnt<<<gN, TB>>>(cnt);
    k_count<<<gE, TB>>>(dst, cnt);
    k_scan<<<1, 1024>>>(cnt, rowptr, cursor, dis, sc);
    k_permute<<<gE, TB>>>(src, dst, dis, cursor, perm_src, perm_coef);

    // layer 1: 128 -> 32
    {
        constexpr int NPB = 256 / (32 / 4);
        k_gemm<128, 32, false><<<(NN + NPB - 1) / NPB, TB>>>(
            x, W1, nullptr, nullptr, nullptr, nullptr, T);
        k_gather<32><<<gW, TB>>>(T, rowptr, perm_src, perm_coef, sc, b1, A);
    }
    // layer 2: 32 -> 64 (bn1+elu fused into gemm input)
    {
        constexpr int NPB = 256 / (64 / 4);
        k_gemm<32, 64, true><<<(NN + NPB - 1) / NPB, TB>>>(
            A, W2, g1, be1, m1, v1, T);
        k_gather<64><<<gW, TB>>>(T, rowptr, perm_src, perm_coef, sc, b2, B);
    }
    // layer 3: 64 -> 128 (bn2+elu fused)
    {
        constexpr int NPB = 256 / (128 / 4);
        k_gemm<64, 128, true><<<(NN + NPB - 1) / NPB, TB>>>(
            B, W3, g2, be2, m2, v2, T);
        k_gather<128><<<gW, TB>>>(T, rowptr, perm_src, perm_coef, sc, b3, A);
    }
    // layer 4: 128 -> 1 (bn3+elu fused), gather + elu + sigmoid -> out
    k_layer4<<<gW, TB>>>(A, W4, g3, be3, m3, v3, t4);
    k_gather1_final<<<gW, TB>>>(t4, rowptr, perm_src, perm_coef, sc, b4, out);
}

// round 6
// speedup vs baseline: 1.3067x; 1.0528x over previous
#include <cuda_runtime.h>
#include <math.h>

#define NN 100000
#define NE 3200000
#define EPS 1e-5f

// ---------------- scratch (static device globals; no allocation) -------------
__device__ int   g_cnt[NN];               // in-degree (without self loop)
__device__ int   g_rowptr[NN + 1];        // CSR row pointers (by dst)
__device__ int   g_cursor[NN];            // fill cursors
__device__ float g_dis[NN];               // deg^-1/2
__device__ float g_sc[NN];                // 1/deg (self-loop coef)
__device__ __align__(8)  int2  g_edge[NE];              // {src, coef bits}, dst-grouped
__device__ __align__(16) float g_T[(size_t)NN * 128];
__device__ __align__(16) float g_A[(size_t)NN * 128];
__device__ __align__(16) float g_B[(size_t)NN * 128];
__device__ float g_t4[NN];

// ---------------- CSR build ---------------------------------------------------
__global__ void __launch_bounds__(256) k_zero_cnt(int* cnt) {
    int i = blockIdx.x * blockDim.x + threadIdx.x;
    if (i < NN) cnt[i] = 0;
}

__global__ void __launch_bounds__(256) k_count(const int* __restrict__ dst, int* cnt) {
    int e = blockIdx.x * blockDim.x + threadIdx.x;
    if (e < NE) atomicAdd(&cnt[dst[e]], 1);
}

// single-block scan: rowptr/cursor = exclusive prefix of cnt; dis/sc from deg=cnt+1
__global__ void __launch_bounds__(1024) k_scan(const int* __restrict__ cnt,
                                               int* rowptr, int* cursor,
                                               float* dis, float* sc) {
    __shared__ int part[1024];
    constexpr int CH = (NN + 1023) / 1024;   // 98
    const int tid = threadIdx.x;
    const int beg = tid * CH;
    const int end = (beg + CH < NN) ? beg + CH : NN;
    int sum = 0;
    for (int i = beg; i < end; ++i) sum += cnt[i];
    part[tid] = sum;
    __syncthreads();
    for (int o = 1; o < 1024; o <<= 1) {
        int v = 0;
        if (tid >= o) v = part[tid - o];
        __syncthreads();
        if (tid >= o) part[tid] += v;
        __syncthreads();
    }
    int run = (tid > 0) ? part[tid - 1] : 0;
    for (int i = beg; i < end; ++i) {
        rowptr[i] = run;
        cursor[i] = run;
        int c = cnt[i];
        run += c;
        float d = (float)(c + 1);
        dis[i] = rsqrtf(d);
        sc[i]  = 1.0f / d;
    }
    if (tid == 1023) rowptr[NN] = part[1023];
}

// permute edges into dst-grouped order; fused coef; single 8B scattered store
__global__ void __launch_bounds__(256) k_permute(const int* __restrict__ src,
                                                 const int* __restrict__ dst,
                                                 const float* __restrict__ dis,
                                                 int* cursor, int2* edges) {
    int e = blockIdx.x * blockDim.x + threadIdx.x;
    if (e >= NE) return;
    int s = src[e], d = dst[e];
    int pos = atomicAdd(&cursor[d], 1);
    edges[pos] = make_int2(s, __float_as_int(dis[s] * dis[d]));
}

// ---------------- GEMM: out = in @ W (+ bias + bn + elu if ACT) ---------------
// Input is NOT activated (it is either raw x or a pre-aggregated feature).
template<int DIN, int DOUT, bool ACT>
__global__ void __launch_bounds__(256) k_gemm(const float* __restrict__ in,
                       const float* __restrict__ W,
                       const float* __restrict__ b,
                       const float* __restrict__ bg, const float* __restrict__ bbe,
                       const float* __restrict__ bm, const float* __restrict__ bv,
                       float* __restrict__ out) {
    constexpr int OX  = DOUT / 4;
    constexpr int NPB = 256 / OX;
    __shared__ __align__(16) float Ws[DIN * DOUT];
    __shared__ float xs[NPB][DIN + 1];
    __shared__ float sh_scale[DOUT];
    __shared__ float sh_shift[DOUT];

    const int tid = threadIdx.x;
    for (int i = tid; i < DIN * DOUT; i += 256) Ws[i] = W[i];
    if (ACT) {
        if (tid < DOUT) {
            float s = bg[tid] * rsqrtf(bv[tid] + EPS);
            sh_scale[tid] = s;
            // bn(z+b) = s*z + (s*(b - m) + be)
            sh_shift[tid] = s * (b[tid] - bm[tid]) + bbe[tid];
        }
    }
    __syncthreads();

    const int base = blockIdx.x * NPB;
    for (int i = tid; i < NPB * DIN; i += 256) {
        int r = i / DIN, k = i - r * DIN;
        int node = base + r;
        xs[r][k] = (node < NN) ? in[(size_t)node * DIN + k] : 0.0f;
    }
    __syncthreads();

    const int ox = tid % OX;
    const int r  = tid / OX;
    const int node = base + r;
    if (node >= NN) return;

    float4 acc = make_float4(0.f, 0.f, 0.f, 0.f);
#pragma unroll
    for (int k = 0; k < DIN; ++k) {
        float xv = xs[r][k];
        float4 w = *reinterpret_cast<const float4*>(&Ws[k * DOUT + ox * 4]);
        acc.x += xv * w.x; acc.y += xv * w.y;
        acc.z += xv * w.z; acc.w += xv * w.w;
    }
    if (ACT) {
        float4 s4 = *reinterpret_cast<const float4*>(&sh_scale[ox * 4]);
        float4 h4 = *reinterpret_cast<const float4*>(&sh_shift[ox * 4]);
        acc.x = acc.x * s4.x + h4.x; acc.y = acc.y * s4.y + h4.y;
        acc.z = acc.z * s4.z + h4.z; acc.w = acc.w * s4.w + h4.w;
        acc.x = (acc.x > 0.f) ? acc.x : expm1f(acc.x);
        acc.y = (acc.y > 0.f) ? acc.y : expm1f(acc.y);
        acc.z = (acc.z > 0.f) ? acc.z : expm1f(acc.z);
        acc.w = (acc.w > 0.f) ? acc.w : expm1f(acc.w);
    }
    *reinterpret_cast<float4*>(&out[(size_t)node * DOUT + ox * 4]) = acc;
}

// ---------------- warp-per-dst CSR gather -------------------------------------
// out[node] = sum_e coef*t[src] + sc[node]*t[node]  (+ bias, bn, elu if ACT)
template<int DIM, bool ACT>
__global__ void __launch_bounds__(256) k_gather(const float* __restrict__ t,
                         const int* __restrict__ rowptr,
                         const int2* __restrict__ edges,
                         const float* __restrict__ sc,
                         const float* __restrict__ b,
                         const float* __restrict__ bg, const float* __restrict__ bbe,
                         const float* __restrict__ bm, const float* __restrict__ bv,
                         float* __restrict__ outp) {
    constexpr int V = DIM / 32;   // floats per lane (1 or 2)
    const int warp = (blockIdx.x * blockDim.x + threadIdx.x) >> 5;
    const int lane = threadIdx.x & 31;
    if (warp >= NN) return;
    const int node = warp;
    const int beg = rowptr[node], end = rowptr[node + 1];

    // per-lane channel params (registers), bias folded into bn shift
    float p_scale[V], p_shift[V];
    if (ACT) {
#pragma unroll
        for (int j = 0; j < V; ++j) {
            int k = lane * V + j;
            float s = bg[k] * rsqrtf(bv[k] + EPS);
            p_scale[j] = s;
            p_shift[j] = s * (b[k] - bm[k]) + bbe[k];
        }
    }

    float acc[V];
#pragma unroll
    for (int j = 0; j < V; ++j) acc[j] = 0.0f;

    int i = beg;
    for (; i + 3 < end; i += 4) {
        int2 e0 = edges[i],   e1 = edges[i+1], e2 = edges[i+2], e3 = edges[i+3];
        float c0 = __int_as_float(e0.y), c1 = __int_as_float(e1.y);
        float c2 = __int_as_float(e2.y), c3 = __int_as_float(e3.y);
        const float* p0 = &t[(size_t)e0.x * DIM + lane * V];
        const float* p1 = &t[(size_t)e1.x * DIM + lane * V];
        const float* p2 = &t[(size_t)e2.x * DIM + lane * V];
        const float* p3 = &t[(size_t)e3.x * DIM + lane * V];
        if constexpr (V == 2) {
            float2 v0 = *reinterpret_cast<const float2*>(p0);
            float2 v1 = *reinterpret_cast<const float2*>(p1);
            float2 v2 = *reinterpret_cast<const float2*>(p2);
            float2 v3 = *reinterpret_cast<const float2*>(p3);
            acc[0] += c0*v0.x + c1*v1.x + c2*v2.x + c3*v3.x;
            acc[1] += c0*v0.y + c1*v1.y + c2*v2.y + c3*v3.y;
        } else {
            acc[0] += c0*p0[0] + c1*p1[0] + c2*p2[0] + c3*p3[0];
        }
    }
    for (; i < end; ++i) {
        int2 e0 = edges[i];
        float c0 = __int_as_float(e0.y);
        const float* p0 = &t[(size_t)e0.x * DIM + lane * V];
        if constexpr (V == 2) {
            float2 v0 = *reinterpret_cast<const float2*>(p0);
            acc[0] += c0 * v0.x; acc[1] += c0 * v0.y;
        } else {
            acc[0] += c0 * p0[0];
        }
    }

    const float s = sc[node];
    const float* ps = &t[(size_t)node * DIM + lane * V];
    float* pa = &outp[(size_t)node * DIM + lane * V];
    float o[V];
    if constexpr (V == 2) {
        float2 v = *reinterpret_cast<const float2*>(ps);
        o[0] = acc[0] + v.x * s;
        o[1] = acc[1] + v.y * s;
    } else {
        o[0] = acc[0] + ps[0] * s;
    }
    if (ACT) {
#pragma unroll
        for (int j = 0; j < V; ++j) {
            float z = o[j] * p_scale[j] + p_shift[j];
            o[j] = (z > 0.f) ? z : expm1f(z);
        }
    }
    if constexpr (V == 2) {
        *reinterpret_cast<float2*>(pa) = make_float2(o[0], o[1]);
    } else {
        pa[0] = o[0];
    }
}

// ---------------- t4 = H4 @ W4 (dim 128 -> 1), H4 already activated ----------
__global__ void __launch_bounds__(256) k_dot(const float* __restrict__ in,
                                             const float* __restrict__ W4,
                                             float* __restrict__ t4) {
    __shared__ float w_s[128];
    int tid = threadIdx.x;
    if (tid < 128) w_s[tid] = W4[tid];
    __syncthreads();
    int warp = tid >> 5, lane = tid & 31;
    int node = blockIdx.x * 8 + warp;
    if (node >= NN) return;
    float acc = 0.0f;
#pragma unroll
    for (int j = 0; j < 4; ++j) {
        int k = j * 32 + lane;
        acc += in[(size_t)node * 128 + k] * w_s[k];
    }
#pragma unroll
    for (int o = 16; o > 0; o >>= 1) acc += __shfl_xor_sync(0xffffffffu, acc, o);
    if (lane == 0) t4[node] = acc;
}

// warp-per-dst gather for dim 1, fused bias+elu+sigmoid -> out
__global__ void __launch_bounds__(256) k_gather1_final(const float* __restrict__ t4,
                                const int* __restrict__ rowptr,
                                const int2* __restrict__ edges,
                                const float* __restrict__ sc,
                                const float* __restrict__ b4,
                                float* __restrict__ out) {
    const int warp = (blockIdx.x * blockDim.x + threadIdx.x) >> 5;
    const int lane = threadIdx.x & 31;
    if (warp >= NN) return;
    const int node = warp;
    const int beg = rowptr[node], end = rowptr[node + 1];
    float acc = 0.0f;
    for (int i = beg + lane; i < end; i += 32) {
        int2 e = edges[i];
        acc += __int_as_float(e.y) * t4[e.x];
    }
#pragma unroll
    for (int o = 16; o > 0; o >>= 1) acc += __shfl_xor_sync(0xffffffffu, acc, o);
    if (lane == 0) {
        float x = acc + t4[node] * sc[node] + b4[0];
        x = (x > 0.0f) ? x : expm1f(x);       // elu
        out[node] = 1.0f / (1.0f + expf(-x)); // sigmoid
    }
}

// ---------------- launch -----------------------------------------------------
extern "C" void kernel_launch(void* const* d_in, const int* in_sizes, int n_in,
                              void* d_out, int out_size) {
    const float* x   = (const float*)d_in[0];
    const int*   src = (const int*)  d_in[1];
    const int*   dst = (const int*)  d_in[2];
    const float* W1 = (const float*)d_in[3];  const float* b1 = (const float*)d_in[4];
    const float* W2 = (const float*)d_in[5];  const float* b2 = (const float*)d_in[6];
    const float* W3 = (const float*)d_in[7];  const float* b3 = (const float*)d_in[8];
    const float* W4 = (const float*)d_in[9];  const float* b4 = (const float*)d_in[10];
    const float* g1 = (const float*)d_in[11]; const float* be1 = (const float*)d_in[12];
    const float* m1 = (const float*)d_in[13]; const float* v1  = (const float*)d_in[14];
    const float* g2 = (const float*)d_in[15]; const float* be2 = (const float*)d_in[16];
    const float* m2 = (const float*)d_in[17]; const float* v2  = (const float*)d_in[18];
    const float* g3 = (const float*)d_in[19]; const float* be3 = (const float*)d_in[20];
    const float* m3 = (const float*)d_in[21]; const float* v3  = (const float*)d_in[22];
    float* out = (float*)d_out;

    void *pcnt, *prp, *pcur, *pdis, *psc, *pedge, *pT, *pA, *pB, *pt4;
    cudaGetSymbolAddress(&pcnt, g_cnt);
    cudaGetSymbolAddress(&prp,  g_rowptr);
    cudaGetSymbolAddress(&pcur, g_cursor);
    cudaGetSymbolAddress(&pdis, g_dis);
    cudaGetSymbolAddress(&psc,  g_sc);
    cudaGetSymbolAddress(&pedge, g_edge);
    cudaGetSymbolAddress(&pT, g_T);
    cudaGetSymbolAddress(&pA, g_A);
    cudaGetSymbolAddress(&pB, g_B);
    cudaGetSymbolAddress(&pt4, g_t4);
    int* cnt = (int*)pcnt; int* rowptr = (int*)prp; int* cursor = (int*)pcur;
    float* dis = (float*)pdis; float* sc = (float*)psc;
    int2* edges = (int2*)pedge;
    float* T = (float*)pT; float* A = (float*)pA; float* B = (float*)pB;
    float* t4 = (float*)pt4;

    const int TB = 256;
    const int gN = (NN + TB - 1) / TB;
    const int gE = (NE + TB - 1) / TB;
    const int gW = (NN + 7) / 8;          // warp-per-node kernels, 8 warps/block

    // CSR build (by dst) + normalization coefficients
    k_zero_cnt<<<gN, TB>>>(cnt);
    k_count<<<gE, TB>>>(dst, cnt);
    k_scan<<<1, 1024>>>(cnt, rowptr, cursor, dis, sc);
    k_permute<<<gE, TB>>>(src, dst, dis, cursor, edges);

    // layer 1: T1 = x@W1 (128->32); gather dim32 + bias+bn1+elu -> H2
    k_gemm<128, 32, false><<<(NN + 31) / 32, TB>>>(
        x, W1, nullptr, nullptr, nullptr, nullptr, nullptr, T);
    k_gather<32, true><<<gW, TB>>>(T, rowptr, edges, sc, b1, g1, be1, m1, v1, A);

    // layer 2: aggregate H2 (dim32) -> AH2; H3 = elu(bn2(AH2@W2 + b2)) (32->64)
    k_gather<32, false><<<gW, TB>>>(A, rowptr, edges, sc,
                                    nullptr, nullptr, nullptr, nullptr, nullptr, B);
    k_gemm<32, 64, true><<<(NN + 15) / 16, TB>>>(B, W2, b2, g2, be2, m2, v2, T);

    // layer 3: aggregate H3 (dim64) -> AH3; H4 = elu(bn3(AH3@W3 + b3)) (64->128)
    k_gather<64, false><<<gW, TB>>>(T, rowptr, edges, sc,
                                    nullptr, nullptr, nullptr, nullptr, nullptr, A);
    k_gemm<64, 128, true><<<(NN + 7) / 8, TB>>>(A, W3, b3, g3, be3, m3, v3, B);

    // layer 4: t4 = H4@W4; gather dim1 + b4 + elu + sigmoid -> out
    k_dot<<<gW, TB>>>(B, W4, t4);
    k_gather1_final<<<gW, TB>>>(t4, rowptr, edges, sc, b4, out);
}

// round 7
// speedup vs baseline: 1.4793x; 1.1321x over previous
#include <cuda_runtime.h>
#include <math.h>

#define NN 100000
#define NE 3200000
#define EPS 1e-5f

// ---------------- scratch (static device globals; no allocation) -------------
__device__ int   g_cnt[NN];
__device__ int   g_rowptr[NN + 1];
__device__ int   g_cursor[NN];
__device__ float g_dis[NN];
__device__ float g_sc[NN];
__device__ __align__(16) int2  g_edge[NE];              // {src, coef bits}, dst-grouped
__device__ __align__(16) float g_T[(size_t)NN * 128];
__device__ __align__(16) float g_A[(size_t)NN * 128];
__device__ __align__(16) float g_B[(size_t)NN * 128];
__device__ float g_t4[NN];

// ---------------- CSR build ---------------------------------------------------
__global__ void __launch_bounds__(256) k_zero_cnt(int* cnt) {
    int i = blockIdx.x * blockDim.x + threadIdx.x;
    if (i < NN) cnt[i] = 0;
}

// 4 edges per thread via int4 load (NE % 4 == 0)
__global__ void __launch_bounds__(256) k_count(const int* __restrict__ dst, int* cnt) {
    int i = blockIdx.x * blockDim.x + threadIdx.x;
    if (i < NE / 4) {
        int4 d4 = reinterpret_cast<const int4*>(dst)[i];
        atomicAdd(&cnt[d4.x], 1);
        atomicAdd(&cnt[d4.y], 1);
        atomicAdd(&cnt[d4.z], 1);
        atomicAdd(&cnt[d4.w], 1);
    }
}

// single-block scan: rowptr/cursor = exclusive prefix of cnt; dis/sc from deg=cnt+1
__global__ void __launch_bounds__(1024) k_scan(const int* __restrict__ cnt,
                                               int* rowptr, int* cursor,
                                               float* dis, float* sc) {
    __shared__ int part[1024];
    constexpr int CH = (NN + 1023) / 1024;   // 98
    const int tid = threadIdx.x;
    const int beg = tid * CH;
    const int end = (beg + CH < NN) ? beg + CH : NN;
    int sum = 0;
    for (int i = beg; i < end; ++i) sum += cnt[i];
    part[tid] = sum;
    __syncthreads();
    for (int o = 1; o < 1024; o <<= 1) {
        int v = 0;
        if (tid >= o) v = part[tid - o];
        __syncthreads();
        if (tid >= o) part[tid] += v;
        __syncthreads();
    }
    int run = (tid > 0) ? part[tid - 1] : 0;
    for (int i = beg; i < end; ++i) {
        rowptr[i] = run;
        cursor[i] = run;
        int c = cnt[i];
        run += c;
        float d = (float)(c + 1);
        dis[i] = rsqrtf(d);
        sc[i]  = 1.0f / d;
    }
    if (tid == 1023) rowptr[NN] = part[1023];
}

__global__ void __launch_bounds__(256) k_permute(const int* __restrict__ src,
                                                 const int* __restrict__ dst,
                                                 const float* __restrict__ dis,
                                                 int* cursor, int2* edges) {
    int e = blockIdx.x * blockDim.x + threadIdx.x;
    if (e >= NE) return;
    int s = src[e], d = dst[e];
    int pos = atomicAdd(&cursor[d], 1);
    edges[pos] = make_int2(s, __float_as_int(dis[s] * dis[d]));
}

// ---------------- GEMM: out = in @ W (+ bias + bn + elu if ACT) ---------------
// R nodes per thread: W float4 read amortized over R FMAs.
template<int DIN, int DOUT, int R, bool ACT>
__global__ void __launch_bounds__(256) k_gemm(const float* __restrict__ in,
                       const float* __restrict__ W,
                       const float* __restrict__ b,
                       const float* __restrict__ bg, const float* __restrict__ bbe,
                       const float* __restrict__ bm, const float* __restrict__ bv,
                       float* __restrict__ out) {
    constexpr int OX  = DOUT / 4;
    constexpr int GR  = 256 / OX;        // row groups per block
    constexpr int NPB = GR * R;          // nodes per block
    __shared__ __align__(16) float Ws[DIN * DOUT];
    __shared__ float xs[NPB][DIN + 1];
    __shared__ float sh_scale[DOUT];
    __shared__ float sh_shift[DOUT];

    const int tid = threadIdx.x;
    for (int i = tid; i < DIN * DOUT; i += 256) Ws[i] = W[i];
    if (ACT) {
        if (tid < DOUT) {
            float s = bg[tid] * rsqrtf(bv[tid] + EPS);
            sh_scale[tid] = s;
            sh_shift[tid] = s * (b[tid] - bm[tid]) + bbe[tid];
        }
    }
    __syncthreads();

    const int base = blockIdx.x * NPB;
    for (int i = tid; i < NPB * DIN; i += 256) {
        int r = i / DIN, k = i - r * DIN;
        int node = base + r;
        xs[r][k] = (node < NN) ? in[(size_t)node * DIN + k] : 0.0f;
    }
    __syncthreads();

    const int ox = tid % OX;
    const int rg = tid / OX;
    const int r0 = rg * R;

    float4 acc[R];
#pragma unroll
    for (int j = 0; j < R; ++j) acc[j] = make_float4(0.f, 0.f, 0.f, 0.f);

#pragma unroll 4
    for (int k = 0; k < DIN; ++k) {
        float4 w = *reinterpret_cast<const float4*>(&Ws[k * DOUT + ox * 4]);
#pragma unroll
        for (int j = 0; j < R; ++j) {
            float xv = xs[r0 + j][k];
            acc[j].x += xv * w.x; acc[j].y += xv * w.y;
            acc[j].z += xv * w.z; acc[j].w += xv * w.w;
        }
    }

    float4 s4, h4;
    if (ACT) {
        s4 = *reinterpret_cast<const float4*>(&sh_scale[ox * 4]);
        h4 = *reinterpret_cast<const float4*>(&sh_shift[ox * 4]);
    }
#pragma unroll
    for (int j = 0; j < R; ++j) {
        int node = base + r0 + j;
        if (node >= NN) continue;
        float4 o = acc[j];
        if (ACT) {
            o.x = o.x * s4.x + h4.x; o.y = o.y * s4.y + h4.y;
            o.z = o.z * s4.z + h4.z; o.w = o.w * s4.w + h4.w;
            o.x = (o.x > 0.f) ? o.x : expm1f(o.x);
            o.y = (o.y > 0.f) ? o.y : expm1f(o.y);
            o.z = (o.z > 0.f) ? o.z : expm1f(o.z);
            o.w = (o.w > 0.f) ? o.w : expm1f(o.w);
        }
        *reinterpret_cast<float4*>(&out[(size_t)node * DOUT + ox * 4]) = o;
    }
}

// ---------------- warp-per-dst CSR gather, unroll x8, dual accumulators -------
template<int DIM, bool ACT>
__global__ void __launch_bounds__(256) k_gather(const float* __restrict__ t,
                         const int* __restrict__ rowptr,
                         const int2* __restrict__ edges,
                         const float* __restrict__ sc,
                         const float* __restrict__ b,
                         const float* __restrict__ bg, const float* __restrict__ bbe,
                         const float* __restrict__ bm, const float* __restrict__ bv,
                         float* __restrict__ outp) {
    constexpr int V = DIM / 32;   // floats per lane (1 or 2)
    const int warp = (blockIdx.x * blockDim.x + threadIdx.x) >> 5;
    const int lane = threadIdx.x & 31;
    if (warp >= NN) return;
    const int node = warp;
    const int beg = rowptr[node], end = rowptr[node + 1];
    const float s = sc[node];

    float p_scale[V], p_shift[V];
    if (ACT) {
#pragma unroll
        for (int j = 0; j < V; ++j) {
            int k = lane * V + j;
            float ss = bg[k] * rsqrtf(bv[k] + EPS);
            p_scale[j] = ss;
            p_shift[j] = ss * (b[k] - bm[k]) + bbe[k];
        }
    }

    float accA[V], accB[V];
#pragma unroll
    for (int j = 0; j < V; ++j) { accA[j] = 0.0f; accB[j] = 0.0f; }

    int i = beg;
    for (; i + 7 < end; i += 8) {
        int2 e[8];
#pragma unroll
        for (int u = 0; u < 8; ++u) e[u] = edges[i + u];
        if constexpr (V == 2) {
            float2 v[8];
#pragma unroll
            for (int u = 0; u < 8; ++u)
                v[u] = *reinterpret_cast<const float2*>(
                    &t[(size_t)e[u].x * DIM + lane * 2]);
#pragma unroll
            for (int u = 0; u < 8; ++u) {
                float c = __int_as_float(e[u].y);
                if (u & 1) { accB[0] += c * v[u].x; accB[1] += c * v[u].y; }
                else       { accA[0] += c * v[u].x; accA[1] += c * v[u].y; }
            }
        } else {
            float v[8];
#pragma unroll
            for (int u = 0; u < 8; ++u)
                v[u] = t[(size_t)e[u].x * DIM + lane];
#pragma unroll
            for (int u = 0; u < 8; ++u) {
                float c = __int_as_float(e[u].y);
                if (u & 1) accB[0] += c * v[u];
                else       accA[0] += c * v[u];
            }
        }
    }
    for (; i < end; ++i) {
        int2 e0 = edges[i];
        float c0 = __int_as_float(e0.y);
        const float* p0 = &t[(size_t)e0.x * DIM + lane * V];
        if constexpr (V == 2) {
            float2 v0 = *reinterpret_cast<const float2*>(p0);
            accA[0] += c0 * v0.x; accA[1] += c0 * v0.y;
        } else {
            accA[0] += c0 * p0[0];
        }
    }

    const float* ps = &t[(size_t)node * DIM + lane * V];
    float* pa = &outp[(size_t)node * DIM + lane * V];
    float o[V];
    if constexpr (V == 2) {
        float2 v = *reinterpret_cast<const float2*>(ps);
        o[0] = accA[0] + accB[0] + v.x * s;
        o[1] = accA[1] + accB[1] + v.y * s;
    } else {
        o[0] = accA[0] + accB[0] + ps[0] * s;
    }
    if (ACT) {
#pragma unroll
        for (int j = 0; j < V; ++j) {
            float z = o[j] * p_scale[j] + p_shift[j];
            o[j] = (z > 0.f) ? z : expm1f(z);
        }
    }
    if constexpr (V == 2) {
        *reinterpret_cast<float2*>(pa) = make_float2(o[0], o[1]);
    } else {
        pa[0] = o[0];
    }
}

// ---------------- t4 = H4 @ W4 (dim 128 -> 1), H4 already activated ----------
__global__ void __launch_bounds__(256) k_dot(const float* __restrict__ in,
                                             const float* __restrict__ W4,
                                             float* __restrict__ t4) {
    __shared__ float w_s[128];
    int tid = threadIdx.x;
    if (tid < 128) w_s[tid] = W4[tid];
    __syncthreads();
    int warp = tid >> 5, lane = tid & 31;
    int node = blockIdx.x * 8 + warp;
    if (node >= NN) return;
    float acc = 0.0f;
#pragma unroll
    for (int j = 0; j < 4; ++j) {
        int k = j * 32 + lane;
        acc += in[(size_t)node * 128 + k] * w_s[k];
    }
#pragma unroll
    for (int o = 16; o > 0; o >>= 1) acc += __shfl_xor_sync(0xffffffffu, acc, o);
    if (lane == 0) t4[node] = acc;
}

__global__ void __launch_bounds__(256) k_gather1_final(const float* __restrict__ t4,
                                const int* __restrict__ rowptr,
                                const int2* __restrict__ edges,
                                const float* __restrict__ sc,
                                const float* __restrict__ b4,
                                float* __restrict__ out) {
    const int warp = (blockIdx.x * blockDim.x + threadIdx.x) >> 5;
    const int lane = threadIdx.x & 31;
    if (warp >= NN) return;
    const int node = warp;
    const int beg = rowptr[node], end = rowptr[node + 1];
    float acc = 0.0f;
    for (int i = beg + lane; i < end; i += 32) {
        int2 e = edges[i];
        acc += __int_as_float(e.y) * t4[e.x];
    }
#pragma unroll
    for (int o = 16; o > 0; o >>= 1) acc += __shfl_xor_sync(0xffffffffu, acc, o);
    if (lane == 0) {
        float x = acc + t4[node] * sc[node] + b4[0];
        x = (x > 0.0f) ? x : expm1f(x);
        out[node] = 1.0f / (1.0f + expf(-x));
    }
}

// ---------------- launch -----------------------------------------------------
extern "C" void kernel_launch(void* const* d_in, const int* in_sizes, int n_in,
                              void* d_out, int out_size) {
    const float* x   = (const float*)d_in[0];
    const int*   src = (const int*)  d_in[1];
    const int*   dst = (const int*)  d_in[2];
    const float* W1 = (const float*)d_in[3];  const float* b1 = (const float*)d_in[4];
    const float* W2 = (const float*)d_in[5];  const float* b2 = (const float*)d_in[6];
    const float* W3 = (const float*)d_in[7];  const float* b3 = (const float*)d_in[8];
    const float* W4 = (const float*)d_in[9];  const float* b4 = (const float*)d_in[10];
    const float* g1 = (const float*)d_in[11]; const float* be1 = (const float*)d_in[12];
    const float* m1 = (const float*)d_in[13]; const float* v1  = (const float*)d_in[14];
    const float* g2 = (const float*)d_in[15]; const float* be2 = (const float*)d_in[16];
    const float* m2 = (const float*)d_in[17]; const float* v2  = (const float*)d_in[18];
    const float* g3 = (const float*)d_in[19]; const float* be3 = (const float*)d_in[20];
    const float* m3 = (const float*)d_in[21]; const float* v3  = (const float*)d_in[22];
    float* out = (float*)d_out;

    void *pcnt, *prp, *pcur, *pdis, *psc, *pedge, *pT, *pA, *pB, *pt4;
    cudaGetSymbolAddress(&pcnt, g_cnt);
    cudaGetSymbolAddress(&prp,  g_rowptr);
    cudaGetSymbolAddress(&pcur, g_cursor);
    cudaGetSymbolAddress(&pdis, g_dis);
    cudaGetSymbolAddress(&psc,  g_sc);
    cudaGetSymbolAddress(&pedge, g_edge);
    cudaGetSymbolAddress(&pT, g_T);
    cudaGetSymbolAddress(&pA, g_A);
    cudaGetSymbolAddress(&pB, g_B);
    cudaGetSymbolAddress(&pt4, g_t4);
    int* cnt = (int*)pcnt; int* rowptr = (int*)prp; int* cursor = (int*)pcur;
    float* dis = (float*)pdis; float* sc = (float*)psc;
    int2* edges = (int2*)pedge;
    float* T = (float*)pT; float* A = (float*)pA; float* B = (float*)pB;
    float* t4 = (float*)pt4;

    const int TB = 256;
    const int gN = (NN + TB - 1) / TB;
    const int gE = (NE + TB - 1) / TB;
    const int gW = (NN + 7) / 8;

    // CSR build; gemm1 reordered before permute (independent of CSR) — also
    // places it at profiled launch index for next-round ncu.
    k_zero_cnt<<<gN, TB>>>(cnt);
    k_count<<<(NE / 4 + TB - 1) / TB, TB>>>(dst, cnt);
    k_scan<<<1, 1024>>>(cnt, rowptr, cursor, dis, sc);
    k_gemm<128, 32, 1, false><<<(NN + 31) / 32, TB>>>(
        x, W1, nullptr, nullptr, nullptr, nullptr, nullptr, T);
    k_permute<<<gE, TB>>>(src, dst, dis, cursor, edges);

    // layer 1: gather dim32 + bias+bn1+elu -> H2
    k_gather<32, true><<<gW, TB>>>(T, rowptr, edges, sc, b1, g1, be1, m1, v1, A);

    // layer 2: aggregate H2 (dim32); H3 = elu(bn2(AH2@W2 + b2))
    k_gather<32, false><<<gW, TB>>>(A, rowptr, edges, sc,
                                    nullptr, nullptr, nullptr, nullptr, nullptr, B);
    k_gemm<32, 64, 4, true><<<(NN + 63) / 64, TB>>>(B, W2, b2, g2, be2, m2, v2, T);

    // layer 3: aggregate H3 (dim64); H4 = elu(bn3(AH3@W3 + b3))
    k_gather<64, false><<<gW, TB>>>(T, rowptr, edges, sc,
                                    nullptr, nullptr, nullptr, nullptr, nullptr, A);
    k_gemm<64, 128, 4, true><<<(NN + 31) / 32, TB>>>(A, W3, b3, g3, be3, m3, v3, B);

    // layer 4
    k_dot<<<gW, TB>>>(B, W4, t4);
    k_gather1_final<<<gW, TB>>>(t4, rowptr, edges, sc, b4, out);
}